// round 6
// baseline (speedup 1.0000x reference)
#include <cuda_runtime.h>
#include <cstdint>

#define B_      64
#define L_      512
#define D_      768
#define NF_     100
#define WAIST_  768
#define KTOT    868     // D_ + NF_

#define BM      128
#define BN      128
#define BK      16
#define ESTR    104     // E / Fs row stride (NF_ padded, zero-filled 100..103)
#define ASTR    136     // As row stride (BM + 8 pad, float4-aligned)
#define KTILES  55      // ceil(880/16): K padded to 880 with zeros

// compaction gather index: gidx[b][j] = source l of j-th valid token, else -1
__device__ int g_gidx[B_ * L_];

// ---------------------------------------------------------------------------
// Kernel 1: per-batch stream compaction index (ballot prefix-sum)
// ---------------------------------------------------------------------------
__global__ void compact_kernel(const int* __restrict__ valid)
{
    int b = blockIdx.x;
    int t = threadIdx.x;                 // 512 threads = L_
    int v = valid[b * L_ + t];
    g_gidx[b * L_ + t] = -1;             // default: zero row

    __shared__ int warp_tot[16];
    unsigned mask = __ballot_sync(0xffffffffu, v != 0);
    int lane = t & 31, w = t >> 5;
    int intra = __popc(mask & ((1u << lane) - 1u));
    if (lane == 31) warp_tot[w] = __popc(mask);
    __syncthreads();                     // also orders the -1 writes
    int offset = 0;
    for (int i = 0; i < w; i++) offset += warp_tot[i];
    if (v) g_gidx[b * L_ + offset + intra] = t;
}

// ---------------------------------------------------------------------------
// Kernel 2: cls head  (64 x 768) @ (768 x 2)
// ---------------------------------------------------------------------------
__global__ void cls_kernel(const float* __restrict__ seq,
                           const float* __restrict__ cls_w,
                           const float* __restrict__ cls_b,
                           float* __restrict__ out)
{
    int b = blockIdx.x;
    int t = threadIdx.x;                 // 256
    const float* row = seq + (size_t)b * L_ * D_;   // l = 0
    float p0 = 0.f, p1 = 0.f;
    for (int d = t; d < D_; d += 256) {
        float x = row[d];
        p0 += x * cls_w[d * 2 + 0];
        p1 += x * cls_w[d * 2 + 1];
    }
    __shared__ float s0[256], s1[256];
    s0[t] = p0; s1[t] = p1;
    __syncthreads();
    for (int s = 128; s > 0; s >>= 1) {
        if (t < s) { s0[t] += s0[t + s]; s1[t] += s1[t + s]; }
        __syncthreads();
    }
    if (t == 0) {
        out[b * 2 + 0] = s0[0] + cls_b[0];
        out[b * 2 + 1] = s1[0] + cls_b[1];
    }
}

// ---------------------------------------------------------------------------
// Kernel 3: fused enrichment + concat + GEMM2 + relu + tag head
//   X[m, 0:768]   = gathered seq rows (or 0)
//   X[m, 768:868] = relu(features @ enr_w + enr_b)
//   h = relu(X @ w1 + b1);  tag = h @ w2 + b2   (h never materialized)
// ---------------------------------------------------------------------------
__global__ __launch_bounds__(256, 2)
void main_kernel(const float* __restrict__ seq,
                 const float* __restrict__ feat,
                 const float* __restrict__ enr_w,
                 const float* __restrict__ enr_b,
                 const float* __restrict__ w1,
                 const float* __restrict__ b1,
                 const float* __restrict__ w2,
                 const float* __restrict__ b2,
                 float* __restrict__ out)
{
    extern __shared__ float sm[];
    float* E   = sm;                  // BM*ESTR  (enriched tile, persists)
    float* SCR = sm + BM * ESTR;      // union: Fs (phase 1) | As+Bs (phase 2)
    __shared__ int   s_src[BM];
    __shared__ float s_tag[BM * 3];

    int b   = blockIdx.y;
    int m0  = blockIdx.x * BM;
    int tid = threadIdx.x;

    if (tid < BM) s_src[tid] = g_gidx[b * L_ + m0 + tid];
    for (int i = tid; i < BM * 3; i += 256) s_tag[i] = 0.f;

    // ---- Phase 1: enrichment tile E[128][104] ----
    float* Fs = SCR;                  // features tile [BM][ESTR]
    for (int i = tid; i < BM * NF_; i += 256) {
        int m = i / NF_, c = i % NF_;
        Fs[m * ESTR + c] = feat[((size_t)(b * L_ + m0 + m)) * NF_ + c];
    }
    __syncthreads();
    // 32 row-quads x 104 cols; 4 rows share one enr_w load
    for (int g = tid; g < 32 * ESTR; g += 256) {
        int f  = g % ESTR;
        int mq = g / ESTR;
        float a0 = 0.f, a1 = 0.f, a2 = 0.f, a3 = 0.f;
        if (f < NF_) {
            float bb = __ldg(&enr_b[f]);
            a0 = bb; a1 = bb; a2 = bb; a3 = bb;
            const float* f0 = Fs + (mq * 4 + 0) * ESTR;
            const float* f1 = Fs + (mq * 4 + 1) * ESTR;
            const float* f2 = Fs + (mq * 4 + 2) * ESTR;
            const float* f3 = Fs + (mq * 4 + 3) * ESTR;
            #pragma unroll 4
            for (int k = 0; k < NF_; k++) {
                float w = __ldg(&enr_w[k * NF_ + f]);
                a0 += f0[k] * w; a1 += f1[k] * w;
                a2 += f2[k] * w; a3 += f3[k] * w;
            }
            a0 = fmaxf(a0, 0.f); a1 = fmaxf(a1, 0.f);
            a2 = fmaxf(a2, 0.f); a3 = fmaxf(a3, 0.f);
        }
        E[(mq * 4 + 0) * ESTR + f] = a0;
        E[(mq * 4 + 1) * ESTR + f] = a1;
        E[(mq * 4 + 2) * ESTR + f] = a2;
        E[(mq * 4 + 3) * ESTR + f] = a3;
    }
    __syncthreads();

    // ---- Phase 2: main GEMM with fused tag epilogue ----
    float* As = SCR;                  // [BK][ASTR]
    float* Bs = SCR + BK * ASTR;      // [BK][BN]
    int ty = tid >> 4, tx = tid & 15;

    for (int nt = 0; nt < WAIST_ / BN; nt++) {
        int n0 = nt * BN;
        float acc[8][8];
        #pragma unroll
        for (int r = 0; r < 8; r++)
            #pragma unroll
            for (int c = 0; c < 8; c++) acc[r][c] = 0.f;

        for (int kt = 0; kt < KTILES; kt++) {
            int k0 = kt * BK;
            __syncthreads();          // protect SCR (prev compute / phase-1 reads)
            // -- load As [BK][BM] (transposed store) --
            if (k0 < D_) {            // gathered seq region (tiles never straddle 768)
                #pragma unroll
                for (int i = 0; i < 2; i++) {
                    int id = tid + i * 256;        // 0..511
                    int m = id >> 2, q = id & 3;
                    int s = s_src[m];
                    float4 v = make_float4(0.f, 0.f, 0.f, 0.f);
                    if (s >= 0)
                        v = *(const float4*)(seq + ((size_t)(b * L_ + s)) * D_ + k0 + q * 4);
                    As[(q * 4 + 0) * ASTR + m] = v.x;
                    As[(q * 4 + 1) * ASTR + m] = v.y;
                    As[(q * 4 + 2) * ASTR + m] = v.z;
                    As[(q * 4 + 3) * ASTR + m] = v.w;
                }
            } else {                  // enriched region: read from E
                #pragma unroll
                for (int i = 0; i < 8; i++) {
                    int id = tid + i * 256;        // 0..2047
                    int m = id >> 4, k = id & 15;
                    int col = k0 + k - D_;         // 0..111
                    As[k * ASTR + m] = (col < ESTR) ? E[m * ESTR + col] : 0.f;
                }
            }
            // -- load Bs [BK][BN] from w1 --
            #pragma unroll
            for (int i = 0; i < 2; i++) {
                int id = tid + i * 256;
                int n4 = id & 31, k = id >> 5;
                int kg = k0 + k;
                float4 v = make_float4(0.f, 0.f, 0.f, 0.f);
                if (kg < KTOT)
                    v = *(const float4*)(w1 + (size_t)kg * WAIST_ + n0 + n4 * 4);
                *(float4*)(Bs + k * BN + n4 * 4) = v;
            }
            __syncthreads();
            // -- 8x8 microtile FMA --
            #pragma unroll
            for (int kk = 0; kk < BK; kk++) {
                float4 av0 = *(const float4*)(As + kk * ASTR + ty * 8);
                float4 av1 = *(const float4*)(As + kk * ASTR + ty * 8 + 4);
                float4 bv0 = *(const float4*)(Bs + kk * BN + tx * 8);
                float4 bv1 = *(const float4*)(Bs + kk * BN + tx * 8 + 4);
                float a[8] = {av0.x, av0.y, av0.z, av0.w, av1.x, av1.y, av1.z, av1.w};
                float bb[8] = {bv0.x, bv0.y, bv0.z, bv0.w, bv1.x, bv1.y, bv1.z, bv1.w};
                #pragma unroll
                for (int r = 0; r < 8; r++)
                    #pragma unroll
                    for (int c = 0; c < 8; c++)
                        acc[r][c] += a[r] * bb[c];
            }
        }

        // -- epilogue: bias + relu + tag-head partial reduction --
        float tg[8][3];
        #pragma unroll
        for (int r = 0; r < 8; r++) { tg[r][0] = 0.f; tg[r][1] = 0.f; tg[r][2] = 0.f; }
        #pragma unroll
        for (int c = 0; c < 8; c++) {
            int n = n0 + tx * 8 + c;
            float bias = __ldg(&b1[n]);
            float w20 = __ldg(&w2[n * 3 + 0]);
            float w21 = __ldg(&w2[n * 3 + 1]);
            float w22 = __ldg(&w2[n * 3 + 2]);
            #pragma unroll
            for (int r = 0; r < 8; r++) {
                float h = fmaxf(acc[r][c] + bias, 0.f);
                tg[r][0] += h * w20;
                tg[r][1] += h * w21;
                tg[r][2] += h * w22;
            }
        }
        // deterministic width-16 butterfly reduction across the 16 column-owners
        #pragma unroll
        for (int r = 0; r < 8; r++)
            #pragma unroll
            for (int t3 = 0; t3 < 3; t3++) {
                float v = tg[r][t3];
                #pragma unroll
                for (int ofs = 8; ofs > 0; ofs >>= 1)
                    v += __shfl_xor_sync(0xffffffffu, v, ofs, 16);
                tg[r][t3] = v;
            }
        if (tx == 0) {
            #pragma unroll
            for (int r = 0; r < 8; r++) {
                int m = ty * 8 + r;
                s_tag[m * 3 + 0] += tg[r][0];
                s_tag[m * 3 + 1] += tg[r][1];
                s_tag[m * 3 + 2] += tg[r][2];
            }
        }
    }
    __syncthreads();
    // tag_logits live at out + 128 (after cls_logits 64x2)
    for (int i = tid; i < BM * 3; i += 256) {
        int m = i / 3, t = i % 3;
        out[128 + ((size_t)(b * L_ + m0 + m)) * 3 + t] = s_tag[i] + __ldg(&b2[t]);
    }
}

// ---------------------------------------------------------------------------
extern "C" void kernel_launch(void* const* d_in, const int* in_sizes, int n_in,
                              void* d_out, int out_size)
{
    const float* seq   = (const float*)d_in[0];
    const float* feat  = (const float*)d_in[1];
    const int*   valid = (const int*)  d_in[2];
    const float* enr_w = (const float*)d_in[3];
    const float* enr_b = (const float*)d_in[4];
    const float* w1    = (const float*)d_in[5];
    const float* b1    = (const float*)d_in[6];
    const float* w2    = (const float*)d_in[7];
    const float* b2    = (const float*)d_in[8];
    const float* cls_w = (const float*)d_in[9];
    const float* cls_b = (const float*)d_in[10];
    float* out = (float*)d_out;

    const int smem = (BM * ESTR + BM * ESTR) * (int)sizeof(float);  // 106,496 B
    cudaFuncSetAttribute(main_kernel, cudaFuncAttributeMaxDynamicSharedMemorySize, smem);

    compact_kernel<<<B_, L_>>>(valid);
    main_kernel<<<dim3(L_ / BM, B_), 256, smem>>>(seq, feat, enr_w, enr_b,
                                                  w1, b1, w2, b2, out);
    cls_kernel<<<B_, 256>>>(seq, cls_w, cls_b, out);
}

// round 8
// speedup vs baseline: 1.1466x; 1.1466x over previous
#include <cuda_runtime.h>
#include <cstdint>

#define B_      64
#define L_      512
#define D_      768
#define NF_     100
#define WAIST_  768
#define KTOT    868     // D_ + NF_

#define BM      128
#define BN      128
#define BK      16
#define ESTR    104     // E / Fs row stride (NF_ padded, zero-filled 100..103)
#define ASTR    136     // As row stride: (k*136+m)%32 unique for k<4,m<8 -> conflict-free
#define BSTR    132     // Bs row stride: (k*132+n)%32 unique for k<4,n<8 -> conflict-free
#define KTILES  55      // ceil(880/16): K padded to 880 with zeros

// compaction gather index: gidx[b][j] = source l of j-th valid token, else -1
__device__ int g_gidx[B_ * L_];

// ---------------------------------------------------------------------------
// Kernel 1: per-batch stream compaction index (ballot prefix-sum)
// ---------------------------------------------------------------------------
__global__ void compact_kernel(const int* __restrict__ valid)
{
    int b = blockIdx.x;
    int t = threadIdx.x;                 // 512 threads = L_
    int v = valid[b * L_ + t];
    g_gidx[b * L_ + t] = -1;             // default: zero row

    __shared__ int warp_tot[16];
    unsigned mask = __ballot_sync(0xffffffffu, v != 0);
    int lane = t & 31, w = t >> 5;
    int intra = __popc(mask & ((1u << lane) - 1u));
    if (lane == 31) warp_tot[w] = __popc(mask);
    __syncthreads();                     // also orders the -1 writes
    int offset = 0;
    for (int i = 0; i < w; i++) offset += warp_tot[i];
    if (v) g_gidx[b * L_ + offset + intra] = t;
}

// ---------------------------------------------------------------------------
// Kernel 2: cls head  (64 x 768) @ (768 x 2)
// ---------------------------------------------------------------------------
__global__ void cls_kernel(const float* __restrict__ seq,
                           const float* __restrict__ cls_w,
                           const float* __restrict__ cls_b,
                           float* __restrict__ out)
{
    int b = blockIdx.x;
    int t = threadIdx.x;                 // 256
    const float* row = seq + (size_t)b * L_ * D_;   // l = 0
    float p0 = 0.f, p1 = 0.f;
    for (int d = t; d < D_; d += 256) {
        float x = row[d];
        p0 += x * cls_w[d * 2 + 0];
        p1 += x * cls_w[d * 2 + 1];
    }
    __shared__ float s0[256], s1[256];
    s0[t] = p0; s1[t] = p1;
    __syncthreads();
    for (int s = 128; s > 0; s >>= 1) {
        if (t < s) { s0[t] += s0[t + s]; s1[t] += s1[t + s]; }
        __syncthreads();
    }
    if (t == 0) {
        out[b * 2 + 0] = s0[0] + cls_b[0];
        out[b * 2 + 1] = s1[0] + cls_b[1];
    }
}

// ---------------------------------------------------------------------------
// tf32 helpers
// ---------------------------------------------------------------------------
__device__ __forceinline__ void split_tf32(float v, uint32_t& hi, uint32_t& lo)
{
    asm("cvt.rna.tf32.f32 %0, %1;" : "=r"(hi) : "f"(v));
    float r = v - __uint_as_float(hi);
    asm("cvt.rna.tf32.f32 %0, %1;" : "=r"(lo) : "f"(r));
}

__device__ __forceinline__ void mma_tf32(float c[4], const uint32_t a[4],
                                         const uint32_t b[2])
{
    asm volatile(
        "mma.sync.aligned.m16n8k8.row.col.f32.tf32.tf32.f32 "
        "{%0,%1,%2,%3},{%4,%5,%6,%7},{%8,%9},{%0,%1,%2,%3};"
        : "+f"(c[0]), "+f"(c[1]), "+f"(c[2]), "+f"(c[3])
        : "r"(a[0]), "r"(a[1]), "r"(a[2]), "r"(a[3]), "r"(b[0]), "r"(b[1]));
}

// ---------------------------------------------------------------------------
// Kernel 3: fused enrichment + concat + GEMM2 (3xTF32 tensor) + relu + tag head
//   X[m, 0:768]   = gathered seq rows (or 0)
//   X[m, 768:868] = relu(features @ enr_w + enr_b)
//   h = relu(X @ w1 + b1);  tag = h @ w2 + b2   (h never materialized)
// Warp grid 2x4: warp (wy,wx) owns rows wy*64..+64, cols wx*32..+32 of the tile.
// ---------------------------------------------------------------------------
__global__ __launch_bounds__(256)
void main_kernel(const float* __restrict__ seq,
                 const float* __restrict__ feat,
                 const float* __restrict__ enr_w,
                 const float* __restrict__ enr_b,
                 const float* __restrict__ w1,
                 const float* __restrict__ b1,
                 const float* __restrict__ w2,
                 const float* __restrict__ b2,
                 float* __restrict__ out)
{
    extern __shared__ float sm[];
    float* E   = sm;                  // BM*ESTR  (enriched tile, persists)
    float* SCR = sm + BM * ESTR;      // union: Fs (phase 1) | As+Bs (phase 2)
    __shared__ int   s_src[BM];
    __shared__ float s_tagp[4][BM][3];   // per-warp-column tag partials

    int b   = blockIdx.y;
    int m0  = blockIdx.x * BM;
    int tid = threadIdx.x;
    int warp = tid >> 5, lane = tid & 31;
    int wy = warp >> 2, wx = warp & 3;   // 2 x 4 warp grid
    int g  = lane >> 2, t4 = lane & 3;   // mma quad indexing

    if (tid < BM) s_src[tid] = g_gidx[b * L_ + m0 + tid];
    for (int i = tid; i < 4 * BM * 3; i += 256)
        (&s_tagp[0][0][0])[i] = 0.f;

    // ---- Phase 1: enrichment tile E[128][104] ----
    float* Fs = SCR;                  // features tile [BM][ESTR]
    for (int i = tid; i < BM * NF_; i += 256) {
        int m = i / NF_, c = i % NF_;
        Fs[m * ESTR + c] = feat[((size_t)(b * L_ + m0 + m)) * NF_ + c];
    }
    __syncthreads();
    for (int gg = tid; gg < 32 * ESTR; gg += 256) {
        int f  = gg % ESTR;
        int mq = gg / ESTR;
        float a0 = 0.f, a1 = 0.f, a2 = 0.f, a3 = 0.f;
        if (f < NF_) {
            float bb = __ldg(&enr_b[f]);
            a0 = bb; a1 = bb; a2 = bb; a3 = bb;
            const float* f0 = Fs + (mq * 4 + 0) * ESTR;
            const float* f1 = Fs + (mq * 4 + 1) * ESTR;
            const float* f2 = Fs + (mq * 4 + 2) * ESTR;
            const float* f3 = Fs + (mq * 4 + 3) * ESTR;
            #pragma unroll 4
            for (int k = 0; k < NF_; k++) {
                float w = __ldg(&enr_w[k * NF_ + f]);
                a0 += f0[k] * w; a1 += f1[k] * w;
                a2 += f2[k] * w; a3 += f3[k] * w;
            }
            a0 = fmaxf(a0, 0.f); a1 = fmaxf(a1, 0.f);
            a2 = fmaxf(a2, 0.f); a3 = fmaxf(a3, 0.f);
        }
        E[(mq * 4 + 0) * ESTR + f] = a0;
        E[(mq * 4 + 1) * ESTR + f] = a1;
        E[(mq * 4 + 2) * ESTR + f] = a2;
        E[(mq * 4 + 3) * ESTR + f] = a3;
    }

    // ---- Phase 2: main GEMM (3xTF32 mma) with fused tag epilogue ----
    float* As = SCR;                  // [BK][ASTR]  (k-major, transposed)
    float* Bs = SCR + BK * ASTR;      // [BK][BSTR]

    for (int nt = 0; nt < WAIST_ / BN; nt++) {
        int n0 = nt * BN;
        float acc[4][4][4];           // [mtile][ntile][frag]
        #pragma unroll
        for (int mt = 0; mt < 4; mt++)
            #pragma unroll
            for (int nn = 0; nn < 4; nn++)
                #pragma unroll
                for (int q = 0; q < 4; q++) acc[mt][nn][q] = 0.f;

        for (int kt = 0; kt < KTILES; kt++) {
            int k0 = kt * BK;
            __syncthreads();          // protect SCR (prev compute / phase-1 reads)
            // -- load As [BK][BM] (transposed store) --
            if (k0 < D_) {            // gathered seq region (tiles never straddle 768)
                #pragma unroll
                for (int i = 0; i < 2; i++) {
                    int id = tid + i * 256;        // 0..511
                    int m = id >> 2, q = id & 3;
                    int s = s_src[m];
                    float4 v = make_float4(0.f, 0.f, 0.f, 0.f);
                    if (s >= 0)
                        v = *(const float4*)(seq + ((size_t)(b * L_ + s)) * D_ + k0 + q * 4);
                    As[(q * 4 + 0) * ASTR + m] = v.x;
                    As[(q * 4 + 1) * ASTR + m] = v.y;
                    As[(q * 4 + 2) * ASTR + m] = v.z;
                    As[(q * 4 + 3) * ASTR + m] = v.w;
                }
            } else {                  // enriched region: read from E
                #pragma unroll
                for (int i = 0; i < 8; i++) {
                    int id = tid + i * 256;        // 0..2047
                    int m = id >> 4, k = id & 15;
                    int col = k0 + k - D_;         // 0..111
                    As[k * ASTR + m] = (col < ESTR) ? E[m * ESTR + col] : 0.f;
                }
            }
            // -- load Bs [BK][BN] from w1 --
            #pragma unroll
            for (int i = 0; i < 2; i++) {
                int id = tid + i * 256;
                int n4 = id & 31, k = id >> 5;
                int kg = k0 + k;
                float4 v = make_float4(0.f, 0.f, 0.f, 0.f);
                if (kg < KTOT)
                    v = *(const float4*)(w1 + (size_t)kg * WAIST_ + n0 + n4 * 4);
                *(float4*)(Bs + k * BSTR + n4 * 4) = v;
            }
            __syncthreads();

            // -- tensor-core compute: 2 k-steps of 8 --
            #pragma unroll
            for (int ks = 0; ks < 2; ks++) {
                int kb = ks * 8;
                uint32_t Ah[4][4], Al[4][4];
                #pragma unroll
                for (int mt = 0; mt < 4; mt++) {
                    int rm = wy * 64 + mt * 16 + g;
                    float a0 = As[(kb + t4)     * ASTR + rm];
                    float a1 = As[(kb + t4)     * ASTR + rm + 8];
                    float a2 = As[(kb + t4 + 4) * ASTR + rm];
                    float a3 = As[(kb + t4 + 4) * ASTR + rm + 8];
                    split_tf32(a0, Ah[mt][0], Al[mt][0]);
                    split_tf32(a1, Ah[mt][1], Al[mt][1]);
                    split_tf32(a2, Ah[mt][2], Al[mt][2]);
                    split_tf32(a3, Ah[mt][3], Al[mt][3]);
                }
                uint32_t Bh[4][2], Bl[4][2];
                #pragma unroll
                for (int nn = 0; nn < 4; nn++) {
                    int nb = wx * 32 + nn * 8 + g;
                    float b0 = Bs[(kb + t4)     * BSTR + nb];
                    float b1v = Bs[(kb + t4 + 4) * BSTR + nb];
                    split_tf32(b0,  Bh[nn][0], Bl[nn][0]);
                    split_tf32(b1v, Bh[nn][1], Bl[nn][1]);
                }
                #pragma unroll
                for (int mt = 0; mt < 4; mt++)
                    #pragma unroll
                    for (int nn = 0; nn < 4; nn++) {
                        mma_tf32(acc[mt][nn], Ah[mt], Bl[nn]);  // small terms first
                        mma_tf32(acc[mt][nn], Al[mt], Bh[nn]);
                        mma_tf32(acc[mt][nn], Ah[mt], Bh[nn]);
                    }
            }
        }

        // -- epilogue: bias + relu + tag-head partial reduction --
        // lane holds C rows (rm+g, rm+g+8), cols 2*t4 and 2*t4+1 per frag
        #pragma unroll
        for (int mt = 0; mt < 4; mt++) {
            float tg0[3] = {0.f, 0.f, 0.f};   // row rm+g
            float tg1[3] = {0.f, 0.f, 0.f};   // row rm+g+8
            #pragma unroll
            for (int nn = 0; nn < 4; nn++) {
                #pragma unroll
                for (int cc = 0; cc < 2; cc++) {
                    int n = n0 + wx * 32 + nn * 8 + 2 * t4 + cc;
                    float bias = __ldg(&b1[n]);
                    float w20 = __ldg(&w2[n * 3 + 0]);
                    float w21 = __ldg(&w2[n * 3 + 1]);
                    float w22 = __ldg(&w2[n * 3 + 2]);
                    float h0 = fmaxf(acc[mt][nn][cc]     + bias, 0.f);
                    float h1 = fmaxf(acc[mt][nn][cc + 2] + bias, 0.f);
                    tg0[0] += h0 * w20; tg0[1] += h0 * w21; tg0[2] += h0 * w22;
                    tg1[0] += h1 * w20; tg1[1] += h1 * w21; tg1[2] += h1 * w22;
                }
            }
            // deterministic reduce over the 4 lanes of the quad (t4)
            #pragma unroll
            for (int t3 = 0; t3 < 3; t3++) {
                tg0[t3] += __shfl_xor_sync(0xffffffffu, tg0[t3], 1);
                tg0[t3] += __shfl_xor_sync(0xffffffffu, tg0[t3], 2);
                tg1[t3] += __shfl_xor_sync(0xffffffffu, tg1[t3], 1);
                tg1[t3] += __shfl_xor_sync(0xffffffffu, tg1[t3], 2);
            }
            if (t4 == 0) {
                int r0 = wy * 64 + mt * 16 + g;
                #pragma unroll
                for (int t3 = 0; t3 < 3; t3++) {
                    s_tagp[wx][r0][t3]     += tg0[t3];
                    s_tagp[wx][r0 + 8][t3] += tg1[t3];
                }
            }
        }
    }
    __syncthreads();
    // tag_logits live at out + 128 (after cls_logits 64x2); fixed-order wx sum
    for (int i = tid; i < BM * 3; i += 256) {
        int m = i / 3, t = i % 3;
        float v = s_tagp[0][m][t] + s_tagp[1][m][t]
                + s_tagp[2][m][t] + s_tagp[3][m][t];
        out[128 + ((size_t)(b * L_ + m0 + m)) * 3 + t] = v + __ldg(&b2[t]);
    }
}

// ---------------------------------------------------------------------------
extern "C" void kernel_launch(void* const* d_in, const int* in_sizes, int n_in,
                              void* d_out, int out_size)
{
    const float* seq   = (const float*)d_in[0];
    const float* feat  = (const float*)d_in[1];
    const int*   valid = (const int*)  d_in[2];
    const float* enr_w = (const float*)d_in[3];
    const float* enr_b = (const float*)d_in[4];
    const float* w1    = (const float*)d_in[5];
    const float* b1    = (const float*)d_in[6];
    const float* w2    = (const float*)d_in[7];
    const float* b2    = (const float*)d_in[8];
    const float* cls_w = (const float*)d_in[9];
    const float* cls_b = (const float*)d_in[10];
    float* out = (float*)d_out;

    const int smem = (BM * ESTR + BM * ESTR) * (int)sizeof(float);  // 106,496 B
    cudaFuncSetAttribute(main_kernel, cudaFuncAttributeMaxDynamicSharedMemorySize, smem);

    compact_kernel<<<B_, L_>>>(valid);
    main_kernel<<<dim3(L_ / BM, B_), 256, smem>>>(seq, feat, enr_w, enr_b,
                                                  w1, b1, w2, b2, out);
    cls_kernel<<<B_, 256>>>(seq, cls_w, cls_b, out);
}

// round 10
// speedup vs baseline: 1.8825x; 1.6418x over previous
#include <cuda_runtime.h>
#include <cuda_bf16.h>
#include <cstdint>

#define B_      64
#define L_      512
#define D_      768
#define NF_     100
#define WAIST_  768
#define KTOT    868     // D_ + NF_

#define BM      128
#define BN      128
#define BK      16
#define ESTR    104     // E / Fs row stride (NF_ padded, zero-filled 100..103)
#define AW      136     // As plane word stride (136 % 32 == 8 -> conflict-free frags)
#define BW      136     // Bs plane word stride
#define KTILES  55      // ceil(880/16): K padded to 880 with zeros

// compaction gather index: gidx[b][j] = source l of j-th valid token, else -1
__device__ int g_gidx[B_ * L_];

// ---------------------------------------------------------------------------
// Kernel 1: per-batch stream compaction index (ballot prefix-sum)
// ---------------------------------------------------------------------------
__global__ void compact_kernel(const int* __restrict__ valid)
{
    int b = blockIdx.x;
    int t = threadIdx.x;                 // 512 threads = L_
    int v = valid[b * L_ + t];
    g_gidx[b * L_ + t] = -1;             // default: zero row

    __shared__ int warp_tot[16];
    unsigned mask = __ballot_sync(0xffffffffu, v != 0);
    int lane = t & 31, w = t >> 5;
    int intra = __popc(mask & ((1u << lane) - 1u));
    if (lane == 31) warp_tot[w] = __popc(mask);
    __syncthreads();                     // also orders the -1 writes
    int offset = 0;
    for (int i = 0; i < w; i++) offset += warp_tot[i];
    if (v) g_gidx[b * L_ + offset + intra] = t;
}

// ---------------------------------------------------------------------------
// Kernel 2: cls head  (64 x 768) @ (768 x 2)
// ---------------------------------------------------------------------------
__global__ void cls_kernel(const float* __restrict__ seq,
                           const float* __restrict__ cls_w,
                           const float* __restrict__ cls_b,
                           float* __restrict__ out)
{
    int b = blockIdx.x;
    int t = threadIdx.x;                 // 256
    const float* row = seq + (size_t)b * L_ * D_;   // l = 0
    float p0 = 0.f, p1 = 0.f;
    for (int d = t; d < D_; d += 256) {
        float x = row[d];
        p0 += x * cls_w[d * 2 + 0];
        p1 += x * cls_w[d * 2 + 1];
    }
    __shared__ float s0[256], s1[256];
    s0[t] = p0; s1[t] = p1;
    __syncthreads();
    for (int s = 128; s > 0; s >>= 1) {
        if (t < s) { s0[t] += s0[t + s]; s1[t] += s1[t + s]; }
        __syncthreads();
    }
    if (t == 0) {
        out[b * 2 + 0] = s0[0] + cls_b[0];
        out[b * 2 + 1] = s1[0] + cls_b[1];
    }
}

// ---------------------------------------------------------------------------
// bf16 split helpers: f = hi + lo (each bf16); pack 2 consecutive-k values.
// ---------------------------------------------------------------------------
__device__ __forceinline__ uint32_t pack_split(float f0, float f1, uint32_t& lo_out)
{
    __nv_bfloat16 h0 = __float2bfloat16(f0);
    __nv_bfloat16 h1 = __float2bfloat16(f1);
    __nv_bfloat16 l0 = __float2bfloat16(f0 - __bfloat162float(h0));
    __nv_bfloat16 l1 = __float2bfloat16(f1 - __bfloat162float(h1));
    __nv_bfloat162 hp; hp.x = h0; hp.y = h1;
    __nv_bfloat162 lp; lp.x = l0; lp.y = l1;
    lo_out = *reinterpret_cast<uint32_t*>(&lp);
    return *reinterpret_cast<uint32_t*>(&hp);
}

__device__ __forceinline__ void mma_bf16(float c[4], const uint32_t a[4],
                                         const uint32_t b[2])
{
    asm volatile(
        "mma.sync.aligned.m16n8k16.row.col.f32.bf16.bf16.f32 "
        "{%0,%1,%2,%3},{%4,%5,%6,%7},{%8,%9},{%0,%1,%2,%3};"
        : "+f"(c[0]), "+f"(c[1]), "+f"(c[2]), "+f"(c[3])
        : "r"(a[0]), "r"(a[1]), "r"(a[2]), "r"(a[3]), "r"(b[0]), "r"(b[1]));
}

// ---------------------------------------------------------------------------
// Kernel 3: fused enrichment + concat + GEMM2 (3-term bf16 mma) + relu + tag
//   X[m, 0:768]   = gathered seq rows (or 0)
//   X[m, 768:868] = relu(features @ enr_w + enr_b)
//   h = relu(X @ w1 + b1);  tag = h @ w2 + b2   (h never materialized)
// Warp grid 2x4: warp (wy,wx) owns rows wy*64..+64, cols wx*32..+32.
// Smem planes store k-pair-packed bf16x2 words: word[j][m] = (k=2j, k=2j+1).
// ---------------------------------------------------------------------------
__global__ __launch_bounds__(256, 2)
void main_kernel(const float* __restrict__ seq,
                 const float* __restrict__ feat,
                 const float* __restrict__ enr_w,
                 const float* __restrict__ enr_b,
                 const float* __restrict__ w1,
                 const float* __restrict__ b1,
                 const float* __restrict__ w2,
                 const float* __restrict__ b2,
                 float* __restrict__ out)
{
    extern __shared__ float sm[];
    float* E   = sm;                  // BM*ESTR  (enriched tile, persists)
    float* SCR = sm + BM * ESTR;      // union: Fs (phase 1) | bf16 planes (phase 2)
    __shared__ int   s_src[BM];
    __shared__ float s_tagp[4][BM][3];   // per-warp-column tag partials

    int b   = blockIdx.y;
    int m0  = blockIdx.x * BM;
    int tid = threadIdx.x;
    int warp = tid >> 5, lane = tid & 31;
    int wy = warp >> 2, wx = warp & 3;   // 2 x 4 warp grid
    int g  = lane >> 2, t4 = lane & 3;   // mma quad indexing

    if (tid < BM) s_src[tid] = g_gidx[b * L_ + m0 + tid];
    for (int i = tid; i < 4 * BM * 3; i += 256)
        (&s_tagp[0][0][0])[i] = 0.f;

    // ---- Phase 1: enrichment tile E[128][104] ----
    float* Fs = SCR;                  // features tile [BM][ESTR] (fp32)
    for (int i = tid; i < BM * NF_; i += 256) {
        int m = i / NF_, c = i % NF_;
        Fs[m * ESTR + c] = feat[((size_t)(b * L_ + m0 + m)) * NF_ + c];
    }
    __syncthreads();
    for (int gg = tid; gg < 32 * ESTR; gg += 256) {
        int f  = gg % ESTR;
        int mq = gg / ESTR;
        float a0 = 0.f, a1 = 0.f, a2 = 0.f, a3 = 0.f;
        if (f < NF_) {
            float bb = __ldg(&enr_b[f]);
            a0 = bb; a1 = bb; a2 = bb; a3 = bb;
            const float* f0 = Fs + (mq * 4 + 0) * ESTR;
            const float* f1 = Fs + (mq * 4 + 1) * ESTR;
            const float* f2 = Fs + (mq * 4 + 2) * ESTR;
            const float* f3 = Fs + (mq * 4 + 3) * ESTR;
            #pragma unroll 4
            for (int k = 0; k < NF_; k++) {
                float w = __ldg(&enr_w[k * NF_ + f]);
                a0 += f0[k] * w; a1 += f1[k] * w;
                a2 += f2[k] * w; a3 += f3[k] * w;
            }
            a0 = fmaxf(a0, 0.f); a1 = fmaxf(a1, 0.f);
            a2 = fmaxf(a2, 0.f); a3 = fmaxf(a3, 0.f);
        }
        E[(mq * 4 + 0) * ESTR + f] = a0;
        E[(mq * 4 + 1) * ESTR + f] = a1;
        E[(mq * 4 + 2) * ESTR + f] = a2;
        E[(mq * 4 + 3) * ESTR + f] = a3;
    }

    // ---- Phase 2: main GEMM (3-term bf16 mma) with fused tag epilogue ----
    uint32_t* as_hi = (uint32_t*)SCR;        // [8][AW]
    uint32_t* as_lo = as_hi + 8 * AW;
    uint32_t* bs_hi = as_lo + 8 * AW;        // [8][BW]
    uint32_t* bs_lo = bs_hi + 8 * BW;

    for (int nt = 0; nt < WAIST_ / BN; nt++) {
        int n0 = nt * BN;
        float acc[4][4][4];           // [mtile][ntile][frag]
        #pragma unroll
        for (int mt = 0; mt < 4; mt++)
            #pragma unroll
            for (int nn = 0; nn < 4; nn++)
                #pragma unroll
                for (int q = 0; q < 4; q++) acc[mt][nn][q] = 0.f;

        for (int kt = 0; kt < KTILES; kt++) {
            int k0 = kt * BK;
            __syncthreads();          // protect SCR (prev compute / phase-1 reads)

            // -- fill A planes: word[j][m] = bf16x2(k=k0+2j, k0+2j+1) of row m --
            if (k0 < D_) {            // gathered seq region (tiles never straddle 768)
                #pragma unroll
                for (int i = 0; i < 2; i++) {
                    int id = tid + i * 256;        // 0..511
                    int m = id >> 2, q = id & 3;
                    int s = s_src[m];
                    float4 v = make_float4(0.f, 0.f, 0.f, 0.f);
                    if (s >= 0)
                        v = *(const float4*)(seq + ((size_t)(b * L_ + s)) * D_ + k0 + q * 4);
                    uint32_t lo;
                    uint32_t hi = pack_split(v.x, v.y, lo);
                    as_hi[(2 * q) * AW + m] = hi;  as_lo[(2 * q) * AW + m] = lo;
                    hi = pack_split(v.z, v.w, lo);
                    as_hi[(2 * q + 1) * AW + m] = hi;  as_lo[(2 * q + 1) * AW + m] = lo;
                }
            } else {                  // enriched region: read from E
                #pragma unroll
                for (int i = 0; i < 4; i++) {
                    int id = tid + i * 256;        // 0..1023
                    int m = id & 127, j = id >> 7;
                    int col0 = k0 + 2 * j - D_;    // 0..110 even
                    float f0 = (col0     < ESTR) ? E[m * ESTR + col0]     : 0.f;
                    float f1 = (col0 + 1 < ESTR) ? E[m * ESTR + col0 + 1] : 0.f;
                    uint32_t lo;
                    uint32_t hi = pack_split(f0, f1, lo);
                    as_hi[j * AW + m] = hi;  as_lo[j * AW + m] = lo;
                }
            }
            // -- fill B planes from w1: word[j][n] = bf16x2(k=k0+2j, +1) at col n --
            #pragma unroll
            for (int i = 0; i < 4; i++) {
                int id = tid + i * 256;            // 0..1023
                int n = id & 127, j = id >> 7;
                int kg = k0 + 2 * j;
                float f0 = (kg     < KTOT) ? __ldg(&w1[(size_t)kg * WAIST_ + n0 + n])       : 0.f;
                float f1 = (kg + 1 < KTOT) ? __ldg(&w1[(size_t)(kg + 1) * WAIST_ + n0 + n]) : 0.f;
                uint32_t lo;
                uint32_t hi = pack_split(f0, f1, lo);
                bs_hi[j * BW + n] = hi;  bs_lo[j * BW + n] = lo;
            }
            __syncthreads();

            // -- tensor compute: one m16n8k16 k-step --
            uint32_t Bh[4][2], Bl[4][2];
            #pragma unroll
            for (int nn = 0; nn < 4; nn++) {
                int nb = wx * 32 + nn * 8 + g;
                Bh[nn][0] = bs_hi[t4 * BW + nb];
                Bh[nn][1] = bs_hi[(t4 + 4) * BW + nb];
                Bl[nn][0] = bs_lo[t4 * BW + nb];
                Bl[nn][1] = bs_lo[(t4 + 4) * BW + nb];
            }
            #pragma unroll
            for (int mt = 0; mt < 4; mt++) {
                int rm = wy * 64 + mt * 16 + g;
                uint32_t Ah[4], Al[4];
                Ah[0] = as_hi[t4 * AW + rm];       Ah[1] = as_hi[t4 * AW + rm + 8];
                Ah[2] = as_hi[(t4 + 4) * AW + rm]; Ah[3] = as_hi[(t4 + 4) * AW + rm + 8];
                Al[0] = as_lo[t4 * AW + rm];       Al[1] = as_lo[t4 * AW + rm + 8];
                Al[2] = as_lo[(t4 + 4) * AW + rm]; Al[3] = as_lo[(t4 + 4) * AW + rm + 8];
                #pragma unroll
                for (int nn = 0; nn < 4; nn++) {
                    mma_bf16(acc[mt][nn], Ah, Bl[nn]);   // small terms first
                    mma_bf16(acc[mt][nn], Al, Bh[nn]);
                    mma_bf16(acc[mt][nn], Ah, Bh[nn]);
                }
            }
        }

        // -- epilogue: bias + relu + tag-head partial reduction --
        // lane holds C rows (rm+g, rm+g+8), cols 2*t4 and 2*t4+1 per frag
        #pragma unroll
        for (int mt = 0; mt < 4; mt++) {
            float tg0[3] = {0.f, 0.f, 0.f};   // row rm+g
            float tg1[3] = {0.f, 0.f, 0.f};   // row rm+g+8
            #pragma unroll
            for (int nn = 0; nn < 4; nn++) {
                #pragma unroll
                for (int cc = 0; cc < 2; cc++) {
                    int n = n0 + wx * 32 + nn * 8 + 2 * t4 + cc;
                    float bias = __ldg(&b1[n]);
                    float w20 = __ldg(&w2[n * 3 + 0]);
                    float w21 = __ldg(&w2[n * 3 + 1]);
                    float w22 = __ldg(&w2[n * 3 + 2]);
                    float h0 = fmaxf(acc[mt][nn][cc]     + bias, 0.f);
                    float h1 = fmaxf(acc[mt][nn][cc + 2] + bias, 0.f);
                    tg0[0] += h0 * w20; tg0[1] += h0 * w21; tg0[2] += h0 * w22;
                    tg1[0] += h1 * w20; tg1[1] += h1 * w21; tg1[2] += h1 * w22;
                }
            }
            // deterministic reduce over the 4 lanes of the quad (t4)
            #pragma unroll
            for (int t3 = 0; t3 < 3; t3++) {
                tg0[t3] += __shfl_xor_sync(0xffffffffu, tg0[t3], 1);
                tg0[t3] += __shfl_xor_sync(0xffffffffu, tg0[t3], 2);
                tg1[t3] += __shfl_xor_sync(0xffffffffu, tg1[t3], 1);
                tg1[t3] += __shfl_xor_sync(0xffffffffu, tg1[t3], 2);
            }
            if (t4 == 0) {
                int r0 = wy * 64 + mt * 16 + g;
                #pragma unroll
                for (int t3 = 0; t3 < 3; t3++) {
                    s_tagp[wx][r0][t3]     += tg0[t3];
                    s_tagp[wx][r0 + 8][t3] += tg1[t3];
                }
            }
        }
    }
    __syncthreads();
    // tag_logits live at out + 128 (after cls_logits 64x2); fixed-order wx sum
    for (int i = tid; i < BM * 3; i += 256) {
        int m = i / 3, t = i % 3;
        float v = s_tagp[0][m][t] + s_tagp[1][m][t]
                + s_tagp[2][m][t] + s_tagp[3][m][t];
        out[128 + ((size_t)(b * L_ + m0 + m)) * 3 + t] = v + __ldg(&b2[t]);
    }
}

// ---------------------------------------------------------------------------
extern "C" void kernel_launch(void* const* d_in, const int* in_sizes, int n_in,
                              void* d_out, int out_size)
{
    const float* seq   = (const float*)d_in[0];
    const float* feat  = (const float*)d_in[1];
    const int*   valid = (const int*)  d_in[2];
    const float* enr_w = (const float*)d_in[3];
    const float* enr_b = (const float*)d_in[4];
    const float* w1    = (const float*)d_in[5];
    const float* b1    = (const float*)d_in[6];
    const float* w2    = (const float*)d_in[7];
    const float* b2    = (const float*)d_in[8];
    const float* cls_w = (const float*)d_in[9];
    const float* cls_b = (const float*)d_in[10];
    float* out = (float*)d_out;

    const int smem = (BM * ESTR + BM * ESTR) * (int)sizeof(float);  // 106,496 B
    cudaFuncSetAttribute(main_kernel, cudaFuncAttributeMaxDynamicSharedMemorySize, smem);

    compact_kernel<<<B_, L_>>>(valid);
    main_kernel<<<dim3(L_ / BM, B_), 256, smem>>>(seq, feat, enr_w, enr_b,
                                                  w1, b1, w2, b2, out);
    cls_kernel<<<B_, 256>>>(seq, cls_w, cls_b, out);
}